// round 7
// baseline (speedup 1.0000x reference)
#include <cuda_runtime.h>
#include <math.h>

#define B_  32
#define N_  512
#define L_  12
#define U_  64
#define HOR 12

constexpr long GT = (long)B_ * N_;          // 16384
constexpr long SZ_NN = (long)B_ * N_ * N_;  // 8388608
constexpr long PB = (long)2048 * 512;       // PTstack per-batch stride

// ---------------------------------------------------------------------------
// Scratch layout (floats)
// ---------------------------------------------------------------------------
constexpr long OFF_A0T  = 0;
constexpr long OFF_A1T  = OFF_A0T + SZ_NN;
constexpr long OFF_PTS  = OFF_A1T + SZ_NN;            // (B, 2048, 512) stacked P_m^T
constexpr long OFF_YG   = OFF_PTS + 4 * SZ_NN;        // (640, 16384)
constexpr long OFF_YC   = OFF_YG + 640 * GT;          // (320, 16384)
constexpr long OFF_RHXT = OFF_YC + 320 * GT;          // (64, 16384)
constexpr long OFF_UT   = OFF_RHXT + 64 * GT;         // (64, 16384)
constexpr long OFF_H    = OFF_UT + 64 * GT;           // 4 x (64,16384) T-layout
constexpr long OFF_HIS  = OFF_H + 4 * 64 * GT;        // (16384, 64) row-major
constexpr long OFF_FC1  = OFF_HIS + 64 * GT;          // (16384, 256)
constexpr long OFF_HISTT= OFF_FC1 + 256 * GT;         // (24, 16384)
constexpr long OFF_DEC  = OFF_HISTT + 24 * GT;        // (16384)
constexpr long OFF_RS0  = OFF_DEC + GT;
constexpr long OFF_RS1  = OFF_RS0 + GT;
constexpr long OFF_WP   = OFF_RS1 + GT;
// repacked weights: e0g(640x68) e0c(320x68) e1g(640x128) e1c(320x128)
//                   d0g(640x68) d0c(320x68) d1g(640x128) d1c(320x128)
constexpr long WP_E0G = OFF_WP;
constexpr long WP_E0C = WP_E0G + 640 * 68;
constexpr long WP_E1G = WP_E0C + 320 * 68;
constexpr long WP_E1C = WP_E1G + 640 * 128;
constexpr long WP_D0G = WP_E1C + 320 * 128;
constexpr long WP_D0C = WP_D0G + 640 * 68;
constexpr long WP_D1G = WP_D0C + 320 * 68;
constexpr long WP_D1C = WP_D1G + 640 * 128;
constexpr long SCRATCH_TOTAL = WP_D1C + 320 * 128;

__device__ float g_scratch[SCRATCH_TOTAL];

// ---------------------------------------------------------------------------
// Support construction
// ---------------------------------------------------------------------------
__global__ void rowsum_k(const float* __restrict__ adj, float* __restrict__ rs0) {
    int w = (blockIdx.x * blockDim.x + threadIdx.x) >> 5;
    int lane = threadIdx.x & 31;
    if (w >= B_ * N_) return;
    const float* base = adj + (long)w * N_;
    float s = 0.f;
    for (int j = lane; j < N_; j += 32) s += base[j];
    #pragma unroll
    for (int o = 16; o; o >>= 1) s += __shfl_xor_sync(0xffffffffu, s, o);
    if (lane == 0) rs0[w] = s + 1.0f;
}

__global__ void colsum_k(const float* __restrict__ adj, float* __restrict__ rs1) {
    int idx = blockIdx.x * blockDim.x + threadIdx.x;
    if (idx >= B_ * N_) return;
    int b = idx >> 9, i = idx & 511;
    const float* base = adj + (long)b * N_ * N_ + i;
    float s = 1.0f;
    for (int j = 0; j < N_; j++) s += base[(long)j * N_];
    rs1[idx] = s;
}

// idx = (b, j, i). A0T[j][i]=A0[i][j], A1T[j][i]=A1[i][j]; PTstack block m=1.
__global__ void fill_supports_T(const float* __restrict__ adj,
                                const float* __restrict__ rs0,
                                const float* __restrict__ rs1,
                                float* __restrict__ A0T, float* __restrict__ A1T,
                                float* __restrict__ PTs) {
    long idx = (long)blockIdx.x * blockDim.x + threadIdx.x;
    if (idx >= (long)B_ * N_ * N_) return;
    int i = (int)(idx & 511);
    long t = idx >> 9;
    int j = (int)(t & 511);
    int b = (int)(t >> 9);
    float d = (i == j) ? 1.f : 0.f;
    float a_ij = adj[((long)b * N_ + i) * N_ + j];
    float a_ji = adj[idx];
    float v0 = (a_ij + d) / rs0[b * N_ + i];
    float v1 = (a_ji + d) / rs1[b * N_ + i];
    A0T[idx] = v0;
    A1T[idx] = v1;
    PTs[(long)b * PB + (long)j * 512 + i] = v0;
}

// W'(5*out x ldw): W'[m*out+c][j] = W[(j*5+m)*out + c] for j<f else 0
__global__ void repack_k(const float* __restrict__ W, float* __restrict__ Wp,
                         int f, int out, int ldw) {
    int idx = blockIdx.x * blockDim.x + threadIdx.x;
    int tot = 5 * out * ldw;
    if (idx >= tot) return;
    int row = idx / ldw, j = idx % ldw;
    int m = row / out, c = row % out;
    Wp[idx] = (j < f) ? W[(long)(j * 5 + m) * out + c] : 0.f;
}

// ---------------------------------------------------------------------------
// Generic batched SGEMM (proven): C[b] = A[b] @ B[b], tile BMxBNx16.
// epi: 0 none, 1: 2x - I, 2: 2x - extra[b] (ld 512), 3: bias + relu
// ---------------------------------------------------------------------------
template<int BM, int BN, int TM, int TN>
__global__ __launch_bounds__(256, 2)
void sgemm_t(int K,
             const float* __restrict__ A, int lda, long sA,
             const float* __restrict__ Bm, int ldb, long sB,
             float* __restrict__ C, int ldc, long sC,
             int epi, const float* __restrict__ extra, long sE,
             const float* __restrict__ bias)
{
    constexpr int BK = 16;
    constexpr int TX = BN / TN;
    constexpr int AF = BM / 64;
    constexpr int BF = BN / 64;
    __shared__ float As[2][BK][BM + 4];
    __shared__ float Bs[2][BK][BN];
    int bz = blockIdx.z;
    const float* Ab = A + (long)bz * sA;
    const float* Bb = Bm + (long)bz * sB;
    float* Cb = C + (long)bz * sC;
    int row0 = blockIdx.y * BM, col0 = blockIdx.x * BN;
    int tid = threadIdx.x;
    int tx = tid % TX, ty = tid / TX;

    int aRow[AF], aCol[AF], bRow[BF], bCol[BF];
    #pragma unroll
    for (int s = 0; s < AF; s++) { int idx = tid + s * 256; aRow[s] = idx >> 2; aCol[s] = (idx & 3) << 2; }
    #pragma unroll
    for (int s = 0; s < BF; s++) { int idx = tid + s * 256; bRow[s] = idx / (BN / 4); bCol[s] = (idx % (BN / 4)) << 2; }

    float4 aR[AF], bR[BF];

    auto ldT = [&](int k0) {
        #pragma unroll
        for (int s = 0; s < AF; s++) {
            const float* p = Ab + (long)(row0 + aRow[s]) * lda + k0 + aCol[s];
            if (k0 + BK <= K) aR[s] = *(const float4*)p;
            else {
                int k = k0 + aCol[s];
                aR[s].x = (k     < K) ? p[0] : 0.f;
                aR[s].y = (k + 1 < K) ? p[1] : 0.f;
                aR[s].z = (k + 2 < K) ? p[2] : 0.f;
                aR[s].w = (k + 3 < K) ? p[3] : 0.f;
            }
        }
        #pragma unroll
        for (int s = 0; s < BF; s++) {
            int k = k0 + bRow[s];
            if (k < K) bR[s] = *(const float4*)(Bb + (long)k * ldb + col0 + bCol[s]);
            else bR[s] = make_float4(0.f, 0.f, 0.f, 0.f);
        }
    };
    auto stT = [&](int buf) {
        #pragma unroll
        for (int s = 0; s < AF; s++) {
            As[buf][aCol[s]    ][aRow[s]] = aR[s].x;
            As[buf][aCol[s] + 1][aRow[s]] = aR[s].y;
            As[buf][aCol[s] + 2][aRow[s]] = aR[s].z;
            As[buf][aCol[s] + 3][aRow[s]] = aR[s].w;
        }
        #pragma unroll
        for (int s = 0; s < BF; s++)
            *(float4*)&Bs[buf][bRow[s]][bCol[s]] = bR[s];
    };

    float acc[TM][TN];
    #pragma unroll
    for (int i = 0; i < TM; i++)
        #pragma unroll
        for (int j = 0; j < TN; j++) acc[i][j] = 0.f;

    int ntile = (K + BK - 1) / BK;
    ldT(0); stT(0); __syncthreads();
    for (int t = 0; t < ntile; t++) {
        if (t + 1 < ntile) ldT((t + 1) * BK);
        int buf = t & 1;
        #pragma unroll
        for (int kk = 0; kk < BK; kk++) {
            float ar[TM], br[TN];
            #pragma unroll
            for (int i = 0; i < TM / 4; i++)
                *(float4*)&ar[i * 4] = *(const float4*)&As[buf][kk][ty * TM + i * 4];
            #pragma unroll
            for (int j = 0; j < TN / 4; j++)
                *(float4*)&br[j * 4] = *(const float4*)&Bs[buf][kk][tx * TN + j * 4];
            #pragma unroll
            for (int i = 0; i < TM; i++)
                #pragma unroll
                for (int j = 0; j < TN; j++) acc[i][j] += ar[i] * br[j];
        }
        if (t + 1 < ntile) stT(buf ^ 1);
        __syncthreads();
    }

    #pragma unroll
    for (int i = 0; i < TM; i++) {
        int r = row0 + ty * TM + i;
        #pragma unroll
        for (int j = 0; j < TN; j++) {
            int c = col0 + tx * TN + j;
            float v = acc[i][j];
            if (epi == 1) v = 2.f * v - ((r == c) ? 1.f : 0.f);
            else if (epi == 2) v = 2.f * v - extra[(long)bz * sE + (long)r * N_ + c];
            else if (epi == 3) { v += bias[c]; v = fmaxf(v, 0.f); }
            Cb[(long)r * ldc + c] = v;
        }
    }
}

// ---------------------------------------------------------------------------
// wxT: Y (M x 16384, ld GT) = W' (M x K, ld ldw) @ Xcat^T (K x 16384)
// Xcat^T row j: j<f_in -> src1 + j*GT, else src2 + (j-f_in)*GT.
// M = gridDim.y*BM exactly; N=16384; K guarded.
// ---------------------------------------------------------------------------
template<int BM, int TM, int TN>
__global__ __launch_bounds__(256, 2)
void wxT_k(int K, int f_in,
           const float* __restrict__ Wp, int ldw,
           const float* __restrict__ src1,
           const float* __restrict__ src2,
           float* __restrict__ Y)
{
    constexpr int BN = 128, BK = 16;
    constexpr int TX = BN / TN;
    constexpr int AF = BM * BK / 1024;   // float4 per thread for A
    constexpr int BF = 2;
    __shared__ float As[2][BK][BM + 4];
    __shared__ float Bs[2][BK][BN];
    int row0 = blockIdx.y * BM, col0 = blockIdx.x * BN;
    int tid = threadIdx.x;
    int tx = tid % TX, ty = tid / TX;

    int aRow[AF], aCol[AF], bRow[BF], bCol[BF];
    #pragma unroll
    for (int s = 0; s < AF; s++) { int idx = tid + s * 256; aRow[s] = idx >> 2; aCol[s] = (idx & 3) << 2; }
    #pragma unroll
    for (int s = 0; s < BF; s++) { int idx = tid + s * 256; bRow[s] = idx >> 5; bCol[s] = (idx & 31) << 2; }

    float4 aR[AF], bR[BF];

    auto ldT = [&](int k0) {
        #pragma unroll
        for (int s = 0; s < AF; s++) {
            const float* p = Wp + (long)(row0 + aRow[s]) * ldw + k0 + aCol[s];
            if (k0 + BK <= K) aR[s] = *(const float4*)p;
            else {
                int k = k0 + aCol[s];
                aR[s].x = (k     < K) ? p[0] : 0.f;
                aR[s].y = (k + 1 < K) ? p[1] : 0.f;
                aR[s].z = (k + 2 < K) ? p[2] : 0.f;
                aR[s].w = (k + 3 < K) ? p[3] : 0.f;
            }
        }
        #pragma unroll
        for (int s = 0; s < BF; s++) {
            int j = k0 + bRow[s];
            float4 v = make_float4(0.f, 0.f, 0.f, 0.f);
            if (j < K) {
                const float* src = (j < f_in) ? (src1 + (long)j * GT)
                                              : (src2 + (long)(j - f_in) * GT);
                v = *(const float4*)(src + col0 + bCol[s]);
            }
            bR[s] = v;
        }
    };
    auto stT = [&](int buf) {
        #pragma unroll
        for (int s = 0; s < AF; s++) {
            As[buf][aCol[s]    ][aRow[s]] = aR[s].x;
            As[buf][aCol[s] + 1][aRow[s]] = aR[s].y;
            As[buf][aCol[s] + 2][aRow[s]] = aR[s].z;
            As[buf][aCol[s] + 3][aRow[s]] = aR[s].w;
        }
        #pragma unroll
        for (int s = 0; s < BF; s++)
            *(float4*)&Bs[buf][bRow[s]][bCol[s]] = bR[s];
    };

    float acc[TM][TN];
    #pragma unroll
    for (int i = 0; i < TM; i++)
        #pragma unroll
        for (int j = 0; j < TN; j++) acc[i][j] = 0.f;

    int ntile = (K + BK - 1) / BK;
    ldT(0); stT(0); __syncthreads();
    for (int t = 0; t < ntile; t++) {
        if (t + 1 < ntile) ldT((t + 1) * BK);
        int buf = t & 1;
        #pragma unroll
        for (int kk = 0; kk < BK; kk++) {
            float ar[TM], br[TN];
            #pragma unroll
            for (int i = 0; i < TM / 4; i++)
                *(float4*)&ar[i * 4] = *(const float4*)&As[buf][kk][ty * TM + i * 4];
            #pragma unroll
            for (int j = 0; j < TN / 4; j++)
                *(float4*)&br[j * 4] = *(const float4*)&Bs[buf][kk][tx * TN + j * 4];
            #pragma unroll
            for (int i = 0; i < TM; i++)
                #pragma unroll
                for (int j = 0; j < TN; j++) acc[i][j] += ar[i] * br[j];
        }
        if (t + 1 < ntile) stT(buf ^ 1);
        __syncthreads();
    }

    #pragma unroll
    for (int i = 0; i < TM; i++) {
        long r = row0 + ty * TM + i;
        #pragma unroll
        for (int j = 0; j < TN; j++) {
            int c = col0 + tx * TN + j;
            Y[r * GT + c] = acc[i][j];
        }
    }
}

// ---------------------------------------------------------------------------
// applyT: out^T_b (OUT x 512) = Y0^T_b + Acat (OUT x 2048) @ PTstack_b (2048x512)
//   Acat[r][k], k=(m-1)*512+j -> Y[((m)*OUT + r... plane (1+(k>>9))]
// MODE 0 (gate): v=sigmoid(v+bias[r]); r<64 -> RHXT[r]=v*HXT[r]; else UT[r-64]=v
// MODE 1 (cand): cc=tanh(v+bias[r]); h = u*hx + (1-u)*cc -> HOUT
// grid (4, 1, 32), block 256.
// ---------------------------------------------------------------------------
template<int OUT, int TM, int TN, int MODE>
__global__ __launch_bounds__(256, 2)
void applyT_k(const float* __restrict__ Y,
              const float* __restrict__ PTs,
              const float* __restrict__ bias,
              const float* __restrict__ HXT,
              float* __restrict__ RHXT,
              float* __restrict__ UT,
              float* __restrict__ HOUT)
{
    constexpr int BM = OUT, BN = 128, BK = 16, K = 2048;
    constexpr int TX = BN / TN;
    constexpr int AE = BM * BK / 256;    // 8 (OUT=128) or 4 (OUT=64)
    constexpr int BF = 2;
    __shared__ float As[2][BK][BM + 4];
    __shared__ float Bs[2][BK][BN];

    int bz = blockIdx.z;
    int col0 = blockIdx.x * BN;
    int tid = threadIdx.x;
    int tx = tid % TX, ty = tid / TX;

    int am = tid % BM;
    int ak0 = (tid / BM) * AE;
    int bRow[BF], bCol[BF];
    #pragma unroll
    for (int s = 0; s < BF; s++) { int idx = tid + s * 256; bRow[s] = idx >> 5; bCol[s] = (idx & 31) << 2; }

    const float* Pb = PTs + (long)bz * PB;
    float aR[AE];
    float4 bR[BF];

    auto ldT = [&](int k0) {
        int k = k0 + ak0;
        int m = k >> 9;            // 0..3 -> plane m+1
        int j = k & 511;
        const float* p = Y + ((long)(m + 1) * OUT + am) * GT + (long)bz * 512 + j;
        #pragma unroll
        for (int e = 0; e < AE; e += 4)
            *(float4*)&aR[e] = *(const float4*)(p + e);
        #pragma unroll
        for (int s = 0; s < BF; s++)
            bR[s] = *(const float4*)(Pb + (long)(k0 + bRow[s]) * 512 + col0 + bCol[s]);
    };
    auto stT = [&](int buf) {
        #pragma unroll
        for (int e = 0; e < AE; e++) As[buf][ak0 + e][am] = aR[e];
        #pragma unroll
        for (int s = 0; s < BF; s++)
            *(float4*)&Bs[buf][bRow[s]][bCol[s]] = bR[s];
    };

    float acc[TM][TN];
    #pragma unroll
    for (int i = 0; i < TM; i++)
        #pragma unroll
        for (int j = 0; j < TN; j++) acc[i][j] = 0.f;

    constexpr int NT = K / BK;
    ldT(0); stT(0); __syncthreads();
    for (int t = 0; t < NT; t++) {
        if (t + 1 < NT) ldT((t + 1) * BK);
        int buf = t & 1;
        #pragma unroll
        for (int kk = 0; kk < BK; kk++) {
            float ar[TM], br[TN];
            #pragma unroll
            for (int i = 0; i < TM / 4; i++)
                *(float4*)&ar[i * 4] = *(const float4*)&As[buf][kk][ty * TM + i * 4];
            #pragma unroll
            for (int j = 0; j < TN / 4; j++)
                *(float4*)&br[j * 4] = *(const float4*)&Bs[buf][kk][tx * TN + j * 4];
            #pragma unroll
            for (int i = 0; i < TM; i++)
                #pragma unroll
                for (int j = 0; j < TN; j++) acc[i][j] += ar[i] * br[j];
        }
        if (t + 1 < NT) stT(buf ^ 1);
        __syncthreads();
    }

    #pragma unroll
    for (int i = 0; i < TM; i++) {
        int r = ty * TM + i;
        #pragma unroll
        for (int j = 0; j < TN; j++) {
            int n = col0 + tx * TN + j;
            long grow = (long)bz * 512 + n;
            float v = acc[i][j] + Y[(long)r * GT + grow] + bias[r];
            if (MODE == 0) {
                v = 1.f / (1.f + expf(-v));
                if (r < 64) RHXT[(long)r * GT + grow] = v * HXT[(long)r * GT + grow];
                else        UT[(long)(r - 64) * GT + grow] = v;
            } else {
                float cc = tanhf(v);
                float u = UT[(long)r * GT + grow];
                float hx = HXT[(long)r * GT + grow];
                HOUT[(long)r * GT + grow] = u * hx + (1.f - u) * cc;
            }
        }
    }
}

// ---------------------------------------------------------------------------
// Small kernels
// ---------------------------------------------------------------------------
// histT[(t*2+c)][b*512+n] = hd[b][t][n][c]
__global__ void hist_t_k(const float* __restrict__ hd, float* __restrict__ histT) {
    int idx = blockIdx.x * blockDim.x + threadIdx.x;
    if (idx >= 24 * B_ * N_) return;
    int n = idx & 511;
    int t2 = idx >> 9;
    int b = t2 & 31;
    int row = t2 >> 5;
    int t = row >> 1, c = row & 1;
    histT[(long)row * GT + b * 512 + n] =
        hd[(((long)b * L_ + t) * N_ + n) * 2 + c];
}

__global__ void add_hisT_k(float* __restrict__ h0T, float* __restrict__ h1T,
                           const float* __restrict__ hisRow) {
    int idx = blockIdx.x * blockDim.x + threadIdx.x;
    if (idx >= (int)(64 * GT)) return;
    int g = idx & 16383;
    int c = idx >> 14;
    float v = hisRow[(long)g * 64 + c];
    h0T[(long)c * GT + g] += v;
    h1T[(long)c * GT + g] += v;
}

__global__ void projT_k(const float* __restrict__ hT, const float* __restrict__ W,
                        const float* __restrict__ bptr, float* __restrict__ decin,
                        float* __restrict__ out, int t) {
    int grow = blockIdx.x * blockDim.x + threadIdx.x;
    if (grow >= B_ * N_) return;
    float s = bptr[0];
    #pragma unroll
    for (int c = 0; c < 64; c++) s += hT[(long)c * GT + grow] * W[c];
    decin[grow] = s;
    out[(long)grow * HOR + t] = s;
}

// ---------------------------------------------------------------------------
// Host orchestration
// ---------------------------------------------------------------------------
static void cellF(float* S, int f_in, const float* xinT, const float* hxT,
                  float* houtT,
                  const float* WgP, int ldwg, const float* bg,
                  const float* WcP, int ldwc, const float* bc) {
    float* PTs = S + OFF_PTS;
    float* YG  = S + OFF_YG;
    float* YC  = S + OFF_YC;
    float* RH  = S + OFF_RHXT;
    float* UT  = S + OFF_UT;
    int K = f_in + 64;

    wxT_k<128, 8, 8><<<dim3(128, 5), 256>>>(K, f_in, WgP, ldwg, xinT, hxT, YG);
    applyT_k<128, 8, 8, 0><<<dim3(4, 1, B_), 256>>>(YG, PTs, bg, hxT, RH, UT, nullptr);
    wxT_k<64, 4, 8><<<dim3(128, 5), 256>>>(K, f_in, WcP, ldwc, xinT, RH, YC);
    applyT_k<64, 4, 8, 1><<<dim3(4, 1, B_), 256>>>(YC, PTs, bc, hxT, nullptr, UT, houtT);
}

extern "C" void kernel_launch(void* const* d_in, const int* in_sizes, int n_in,
                              void* d_out, int out_size) {
    (void)in_sizes; (void)n_in; (void)out_size;
    float* S = nullptr;
    cudaGetSymbolAddress((void**)&S, g_scratch);

    const float* hd   = (const float*)d_in[0];
    const float* hs   = (const float*)d_in[1];
    const float* adj  = (const float*)d_in[2];
    const float* e0Wg = (const float*)d_in[3];
    const float* e0bg = (const float*)d_in[4];
    const float* e0Wc = (const float*)d_in[5];
    const float* e0bc = (const float*)d_in[6];
    const float* e1Wg = (const float*)d_in[7];
    const float* e1bg = (const float*)d_in[8];
    const float* e1Wc = (const float*)d_in[9];
    const float* e1bc = (const float*)d_in[10];
    const float* d0Wg = (const float*)d_in[11];
    const float* d0bg = (const float*)d_in[12];
    const float* d0Wc = (const float*)d_in[13];
    const float* d0bc = (const float*)d_in[14];
    const float* d1Wg = (const float*)d_in[15];
    const float* d1bg = (const float*)d_in[16];
    const float* d1Wc = (const float*)d_in[17];
    const float* d1bc = (const float*)d_in[18];
    const float* prW  = (const float*)d_in[19];
    const float* prb  = (const float*)d_in[20];
    const float* f1W  = (const float*)d_in[21];
    const float* f1b  = (const float*)d_in[22];
    const float* f2W  = (const float*)d_in[23];
    const float* f2b  = (const float*)d_in[24];
    float* out = (float*)d_out;

    float* A0T  = S + OFF_A0T;
    float* A1T  = S + OFF_A1T;
    float* PTs  = S + OFF_PTS;
    float* HIS  = S + OFF_HIS;
    float* FC1  = S + OFF_FC1;
    float* HISTT= S + OFF_HISTT;
    float* DEC  = S + OFF_DEC;
    float* RS0  = S + OFF_RS0;
    float* RS1  = S + OFF_RS1;

    float* Hbuf[4];
    for (int i = 0; i < 4; i++) Hbuf[i] = S + OFF_H + (long)i * 64 * GT;

    cudaMemsetAsync(S + OFF_H, 0, 2 * 64 * GT * sizeof(float));  // h0, h1
    cudaMemsetAsync(DEC, 0, GT * sizeof(float));

    // ---- repack weights (W' layout, once per call) ----
    repack_k<<<(640 * 68 + 255) / 256, 256>>>(e0Wg, S + WP_E0G, 66, 128, 68);
    repack_k<<<(320 * 68 + 255) / 256, 256>>>(e0Wc, S + WP_E0C, 66, 64, 68);
    repack_k<<<(640 * 128 + 255) / 256, 256>>>(e1Wg, S + WP_E1G, 128, 128, 128);
    repack_k<<<(320 * 128 + 255) / 256, 256>>>(e1Wc, S + WP_E1C, 128, 64, 128);
    repack_k<<<(640 * 68 + 255) / 256, 256>>>(d0Wg, S + WP_D0G, 65, 128, 68);
    repack_k<<<(320 * 68 + 255) / 256, 256>>>(d0Wc, S + WP_D0C, 65, 64, 68);
    repack_k<<<(640 * 128 + 255) / 256, 256>>>(d1Wg, S + WP_D1G, 128, 128, 128);
    repack_k<<<(320 * 128 + 255) / 256, 256>>>(d1Wc, S + WP_D1C, 128, 64, 128);

    // ---- supports + stacked P^T operator ----
    rowsum_k<<<(B_ * N_ * 32 + 255) / 256, 256>>>(adj, RS0);
    colsum_k<<<(B_ * N_ + 255) / 256, 256>>>(adj, RS1);
    fill_supports_T<<<(int)(((long)B_ * N_ * N_ + 255) / 256), 256>>>(adj, RS0, RS1, A0T, A1T, PTs);
    const long NB = (long)N_ * N_;
    dim3 gp(4, 4, B_);
    // block m=2 rows [512,1024): 2*A0T@A0T - I
    sgemm_t<128, 128, 8, 8><<<gp, 256>>>(512, A0T, 512, NB, A0T, 512, NB,
                                         PTs + 512 * 512, 512, PB, 1, nullptr, 0, nullptr);
    // block m=3 rows [1024,1536): A0T@A1T
    sgemm_t<128, 128, 8, 8><<<gp, 256>>>(512, A0T, 512, NB, A1T, 512, NB,
                                         PTs + 2 * 512 * 512, 512, PB, 0, nullptr, 0, nullptr);
    // block m=4 rows [1536,2048): 2*(m3)@A1T - A0T
    sgemm_t<128, 128, 8, 8><<<gp, 256>>>(512, PTs + 2 * 512 * 512, 512, PB, A1T, 512, NB,
                                         PTs + 3 * 512 * 512, 512, PB, 2, A0T, NB, nullptr);

    // ---- fc_his ----
    sgemm_t<128, 128, 8, 8><<<dim3(2, 128, 1), 256>>>(96, hs, 96, 0, f1W, 256, 0,
                                                      FC1, 256, 0, 3, nullptr, 0, f1b);
    sgemm_t<128, 64, 8, 4><<<dim3(1, 128, 1), 256>>>(256, FC1, 256, 0, f2W, 64, 0,
                                                     HIS, 64, 0, 3, nullptr, 0, f2b);

    // ---- encoder inputs in T layout ----
    hist_t_k<<<(24 * B_ * N_ + 255) / 256, 256>>>(hd, HISTT);

    float *hc0 = Hbuf[0], *hc1 = Hbuf[1], *hn0 = Hbuf[2], *hn1 = Hbuf[3];

    // ---- encoder ----
    for (int t = 0; t < L_; t++) {
        cellF(S, 2, HISTT + (long)t * 2 * GT, hc0, hn0,
              S + WP_E0G, 68, e0bg, S + WP_E0C, 68, e0bc);
        cellF(S, 64, hn0, hc1, hn1,
              S + WP_E1G, 128, e1bg, S + WP_E1C, 128, e1bc);
        float* tmp;
        tmp = hc0; hc0 = hn0; hn0 = tmp;
        tmp = hc1; hc1 = hn1; hn1 = tmp;
    }
    add_hisT_k<<<(int)((64 * GT + 255) / 256), 256>>>(hc0, hc1, HIS);

    // ---- decoder ----
    for (int t = 0; t < HOR; t++) {
        cellF(S, 1, DEC, hc0, hn0,
              S + WP_D0G, 68, d0bg, S + WP_D0C, 68, d0bc);
        cellF(S, 64, hn0, hc1, hn1,
              S + WP_D1G, 128, d1bg, S + WP_D1C, 128, d1bc);
        projT_k<<<(B_ * N_ + 255) / 256, 256>>>(hn1, prW, prb, DEC, out, t);
        float* tmp;
        tmp = hc0; hc0 = hn0; hn0 = tmp;
        tmp = hc1; hc1 = hn1; hn1 = tmp;
    }
}

// round 8
// speedup vs baseline: 1.2705x; 1.2705x over previous
#include <cuda_runtime.h>
#include <math.h>

#define B_  32
#define N_  512
#define L_  12
#define U_  64
#define HOR 12

// ---------------------------------------------------------------------------
// Scratch layout (floats)
// ---------------------------------------------------------------------------
constexpr long SZ_NN  = (long)B_ * N_ * N_;          // 8388608
constexpr long GT     = (long)B_ * N_;               // 16384 (global T-layout row stride)

constexpr long OFF_A0T   = 0;
constexpr long OFF_A1T   = OFF_A0T + SZ_NN;
constexpr long OFF_PT    = OFF_A1T + SZ_NN;              // (B,512,2048)  P^T blocks
constexpr long OFF_TCATT = OFF_PT + 4 * SZ_NN;           // (B,128,2048)
constexpr long OFF_THXT  = OFF_TCATT + (long)B_*128*2048; // (B,64,2048)
constexpr long OFF_TRHXT = OFF_THXT + (long)B_*64*2048;   // (B,64,2048)
constexpr long OFF_TTX   = OFF_TRHXT + (long)B_*64*2048;  // (B,24,2048) enc xin diff
constexpr long OFF_TDEC  = OFF_TTX + (long)B_*24*2048;    // (B,2048)
constexpr long OFF_HISTT = OFF_TDEC + (long)B_*2048;      // (24,16384)
constexpr long OFF_U     = OFF_HISTT + 24*GT;             // (16384,64) row
constexpr long OFF_HIS   = OFF_U + 64*GT;                 // (16384,64) row
constexpr long OFF_FC1   = OFF_HIS + 64*GT;               // (16384,256)
constexpr long OFF_DEC   = OFF_FC1 + 256*GT;              // (16384)
constexpr long OFF_RS0   = OFF_DEC + GT;
constexpr long OFF_RS1   = OFF_RS0 + GT;
constexpr long OFF_RHXT  = OFF_RS1 + GT;                  // (64,16384)
constexpr long OFF_H     = OFF_RHXT + 64*GT;              // 8 buffers x 1M
constexpr long SZ_H1 = 64*GT;
constexpr long SCRATCH_TOTAL = OFF_H + 8*SZ_H1;

__device__ float g_scratch[SCRATCH_TOTAL];

// ---------------------------------------------------------------------------
// Support construction (transposed supports)
// ---------------------------------------------------------------------------
__global__ void rowsum_k(const float* __restrict__ adj, float* __restrict__ rs0) {
    int w = (blockIdx.x * blockDim.x + threadIdx.x) >> 5;
    int lane = threadIdx.x & 31;
    if (w >= B_ * N_) return;
    const float* base = adj + (long)w * N_;
    float s = 0.f;
    for (int j = lane; j < N_; j += 32) s += base[j];
    #pragma unroll
    for (int o = 16; o; o >>= 1) s += __shfl_xor_sync(0xffffffffu, s, o);
    if (lane == 0) rs0[w] = s + 1.0f;
}

__global__ void colsum_k(const float* __restrict__ adj, float* __restrict__ rs1) {
    int idx = blockIdx.x * blockDim.x + threadIdx.x;
    if (idx >= B_ * N_) return;
    int b = idx >> 9, i = idx & 511;
    const float* base = adj + (long)b * N_ * N_ + i;
    float s = 1.0f;
    for (int j = 0; j < N_; j++) s += base[(long)j * N_];
    rs1[idx] = s;
}

// idx = (b, j, i), i fastest. A0T[j][i] = A0[i][j], A1T[j][i] = A1[i][j].
__global__ void fill_supports_T(const float* __restrict__ adj,
                                const float* __restrict__ rs0,
                                const float* __restrict__ rs1,
                                float* __restrict__ A0T, float* __restrict__ A1T,
                                float* __restrict__ PT) {
    long idx = (long)blockIdx.x * blockDim.x + threadIdx.x;
    if (idx >= (long)B_ * N_ * N_) return;
    int i = (int)(idx & 511);
    long t = idx >> 9;
    int j = (int)(t & 511);
    int b = (int)(t >> 9);
    float d = (i == j) ? 1.f : 0.f;
    float a_ij = adj[((long)b * N_ + i) * N_ + j];   // strided read
    float a_ji = adj[idx];                           // coalesced
    float v0 = (a_ij + d) / rs0[b * N_ + i];         // A0[i][j]
    float v1 = (a_ji + d) / rs1[b * N_ + i];         // A1[i][j]
    A0T[idx] = v0;
    A1T[idx] = v1;
    PT[(long)b * 512 * 2048 + (long)j * 2048 + i] = v0;  // block m=1 cols [0,512)
}

// ---------------------------------------------------------------------------
// Generic batched SGEMM: C[b] = A[b] @ B[b], tile BMxBNx16.
// epi: 0 none, 1: 2x - I, 2: 2x - extra[b] (ld 512), 3: bias + relu
// ---------------------------------------------------------------------------
template<int BM, int BN, int TM, int TN>
__global__ __launch_bounds__(256, 2)
void sgemm_t(int K,
             const float* __restrict__ A, int lda, long sA,
             const float* __restrict__ Bm, int ldb, long sB,
             float* __restrict__ C, int ldc, long sC,
             int epi, const float* __restrict__ extra, long sE,
             const float* __restrict__ bias)
{
    constexpr int BK = 16;
    constexpr int TX = BN / TN;
    constexpr int AF = BM / 64;
    constexpr int BF = BN / 64;
    __shared__ float As[2][BK][BM + 4];
    __shared__ float Bs[2][BK][BN];
    int bz = blockIdx.z;
    const float* Ab = A + (long)bz * sA;
    const float* Bb = Bm + (long)bz * sB;
    float* Cb = C + (long)bz * sC;
    int row0 = blockIdx.y * BM, col0 = blockIdx.x * BN;
    int tid = threadIdx.x;
    int tx = tid % TX, ty = tid / TX;

    int aRow[AF], aCol[AF], bRow[BF], bCol[BF];
    #pragma unroll
    for (int s = 0; s < AF; s++) { int idx = tid + s * 256; aRow[s] = idx >> 2; aCol[s] = (idx & 3) << 2; }
    #pragma unroll
    for (int s = 0; s < BF; s++) { int idx = tid + s * 256; bRow[s] = idx / (BN / 4); bCol[s] = (idx % (BN / 4)) << 2; }

    float4 aR[AF], bR[BF];

    auto ldT = [&](int k0) {
        #pragma unroll
        for (int s = 0; s < AF; s++) {
            const float* p = Ab + (long)(row0 + aRow[s]) * lda + k0 + aCol[s];
            if (k0 + BK <= K) aR[s] = *(const float4*)p;
            else {
                int k = k0 + aCol[s];
                aR[s].x = (k     < K) ? p[0] : 0.f;
                aR[s].y = (k + 1 < K) ? p[1] : 0.f;
                aR[s].z = (k + 2 < K) ? p[2] : 0.f;
                aR[s].w = (k + 3 < K) ? p[3] : 0.f;
            }
        }
        #pragma unroll
        for (int s = 0; s < BF; s++) {
            int k = k0 + bRow[s];
            if (k < K) bR[s] = *(const float4*)(Bb + (long)k * ldb + col0 + bCol[s]);
            else bR[s] = make_float4(0.f, 0.f, 0.f, 0.f);
        }
    };
    auto stT = [&](int buf) {
        #pragma unroll
        for (int s = 0; s < AF; s++) {
            As[buf][aCol[s]    ][aRow[s]] = aR[s].x;
            As[buf][aCol[s] + 1][aRow[s]] = aR[s].y;
            As[buf][aCol[s] + 2][aRow[s]] = aR[s].z;
            As[buf][aCol[s] + 3][aRow[s]] = aR[s].w;
        }
        #pragma unroll
        for (int s = 0; s < BF; s++)
            *(float4*)&Bs[buf][bRow[s]][bCol[s]] = bR[s];
    };

    float acc[TM][TN];
    #pragma unroll
    for (int i = 0; i < TM; i++)
        #pragma unroll
        for (int j = 0; j < TN; j++) acc[i][j] = 0.f;

    int ntile = (K + BK - 1) / BK;
    ldT(0); stT(0); __syncthreads();
    for (int t = 0; t < ntile; t++) {
        if (t + 1 < ntile) ldT((t + 1) * BK);
        int buf = t & 1;
        #pragma unroll
        for (int kk = 0; kk < BK; kk++) {
            float ar[TM], br[TN];
            #pragma unroll
            for (int i = 0; i < TM / 4; i++)
                *(float4*)&ar[i * 4] = *(const float4*)&As[buf][kk][ty * TM + i * 4];
            #pragma unroll
            for (int j = 0; j < TN / 4; j++)
                *(float4*)&br[j * 4] = *(const float4*)&Bs[buf][kk][tx * TN + j * 4];
            #pragma unroll
            for (int i = 0; i < TM; i++)
                #pragma unroll
                for (int j = 0; j < TN; j++) acc[i][j] += ar[i] * br[j];
        }
        if (t + 1 < ntile) stT(buf ^ 1);
        __syncthreads();
    }

    #pragma unroll
    for (int i = 0; i < TM; i++) {
        int r = row0 + ty * TM + i;
        #pragma unroll
        for (int j = 0; j < TN; j++) {
            int c = col0 + tx * TN + j;
            float v = acc[i][j];
            if (epi == 1) v = 2.f * v - ((r == c) ? 1.f : 0.f);
            else if (epi == 2) v = 2.f * v - extra[(long)bz * sE + (long)r * N_ + c];
            else if (epi == 3) { v += bias[c]; v = fmaxf(v, 0.f); }
            Cb[(long)r * ldc + c] = v;
        }
    }
}

// ---------------------------------------------------------------------------
// Transposed diffusion GEMM:
//   TT[b](MR x 2048) = Aeff[b](MR x 512) @ PT[b](512 x 2048)
// Aeff row r: r < asplit -> src1[r*16384 + b*512 + k]
//             else (r < MR) -> src2[(r-asplit)*16384 + b*512 + k]
// ---------------------------------------------------------------------------
template<int BM, int BN, int TM, int TN>
__global__ __launch_bounds__(256, 2)
void difft_k(int MR, int asplit,
             const float* __restrict__ src1,
             const float* __restrict__ src2,
             const float* __restrict__ PT,
             float* __restrict__ TT, long sT)
{
    constexpr int BK = 16;
    constexpr int TX = BN / TN;
    constexpr int AE = BM * BK / 256;     // floats per thread (contig k)
    constexpr int BF = BK * BN / 1024;
    __shared__ float As[2][BK][BM + 4];
    __shared__ float Bs[2][BK][BN];

    int bz = blockIdx.z;
    int row0 = blockIdx.y * BM, col0 = blockIdx.x * BN;
    int tid = threadIdx.x;
    int tx = tid % TX, ty = tid / TX;

    int am = tid % BM;
    int ak0 = (tid / BM) * AE;
    int r = row0 + am;
    const float* srow = nullptr;
    if (r < asplit) srow = src1 + (long)r * GT + (long)bz * 512;
    else if (r < MR) srow = src2 + (long)(r - asplit) * GT + (long)bz * 512;

    int bRow[BF], bCol[BF];
    #pragma unroll
    for (int s = 0; s < BF; s++) {
        int idx = tid + s * 256;
        bRow[s] = idx / (BN / 4);
        bCol[s] = (idx % (BN / 4)) << 2;
    }

    float aR[AE];
    float4 bR[BF];
    const float* Pb = PT + (long)bz * 512 * 2048;

    auto ldT = [&](int k0) {
        if (srow) {
            #pragma unroll
            for (int e = 0; e < AE; e += 4)
                *(float4*)&aR[e] = *(const float4*)(srow + k0 + ak0 + e);
        } else {
            #pragma unroll
            for (int e = 0; e < AE; e++) aR[e] = 0.f;
        }
        #pragma unroll
        for (int s = 0; s < BF; s++)
            bR[s] = *(const float4*)(Pb + (long)(k0 + bRow[s]) * 2048 + col0 + bCol[s]);
    };
    auto stT = [&](int buf) {
        #pragma unroll
        for (int e = 0; e < AE; e++) As[buf][ak0 + e][am] = aR[e];
        #pragma unroll
        for (int s = 0; s < BF; s++) *(float4*)&Bs[buf][bRow[s]][bCol[s]] = bR[s];
    };

    float acc[TM][TN];
    #pragma unroll
    for (int i = 0; i < TM; i++)
        #pragma unroll
        for (int j = 0; j < TN; j++) acc[i][j] = 0.f;

    constexpr int NT = 512 / BK;
    ldT(0); stT(0); __syncthreads();
    for (int t = 0; t < NT; t++) {
        if (t + 1 < NT) ldT((t + 1) * BK);
        int buf = t & 1;
        #pragma unroll
        for (int kk = 0; kk < BK; kk++) {
            float ar[TM], br[TN];
            #pragma unroll
            for (int i = 0; i < TM / 4; i++)
                *(float4*)&ar[i * 4] = *(const float4*)&As[buf][kk][ty * TM + i * 4];
            #pragma unroll
            for (int j = 0; j < TN / 4; j++)
                *(float4*)&br[j * 4] = *(const float4*)&Bs[buf][kk][tx * TN + j * 4];
            #pragma unroll
            for (int i = 0; i < TM; i++)
                #pragma unroll
                for (int j = 0; j < TN; j++) acc[i][j] += ar[i] * br[j];
        }
        if (t + 1 < NT) stT(buf ^ 1);
        __syncthreads();
    }

    float* Tb = TT + (long)bz * sT;
    #pragma unroll
    for (int i = 0; i < TM; i++) {
        int rr = row0 + ty * TM + i;
        if (rr < MR) {
            #pragma unroll
            for (int j = 0; j < TN; j++) {
                int c = col0 + tx * TN + j;
                Tb[(long)rr * 2048 + c] = acc[i][j];
            }
        }
    }
}

// ---------------------------------------------------------------------------
// Contraction GEMM, transposed (coalesced) A-gather.
// ---------------------------------------------------------------------------
template<int BM, int BN, int TM, int TN>
__global__ __launch_bounds__(256, 2)
void catgemmT_k(int K, int f_in,
                const float* __restrict__ Xa, long sXa, int snXa, long sjXa,
                const float* __restrict__ XbT,
                const float* __restrict__ Ta, long sTa,
                const float* __restrict__ Tb, long sTb,
                const float* __restrict__ W, int ldW,
                const float* __restrict__ bias,
                const float* __restrict__ HXrow,
                const float* __restrict__ Urow,
                float* __restrict__ RHXT, float* __restrict__ Uout,
                float* __restrict__ HoutT, float* __restrict__ HoutR,
                int mode)
{
    constexpr int BK = 16;
    constexpr int TX = BN / TN;
    constexpr int AE = BM * BK / 256;
    constexpr int BF = BK * BN / 1024;
    __shared__ float As[2][BK][BM + 4];
    __shared__ float Bs[2][BK][BN];

    int row0 = blockIdx.y * BM;
    int col0 = blockIdx.x * BN;
    int tid = threadIdx.x;
    int tx = tid % TX, ty = tid / TX;

    int am = tid % BM;
    int ak0 = (tid / BM) * AE;
    int growL = row0 + am;
    int bL = growL >> 9, nL = growL & 511;

    int bRow[BF], bCol[BF];
    #pragma unroll
    for (int s = 0; s < BF; s++) {
        int idx = tid + s * 256;
        bRow[s] = idx / (BN / 4);
        bCol[s] = (idx % (BN / 4)) << 2;
    }

    float aR[AE];
    float4 bR[BF];

    auto ldT = [&](int k0) {
        #pragma unroll
        for (int e = 0; e < AE; e++) {
            int k = k0 + ak0 + e;
            float v = 0.f;
            if (k < K) {
                int j = k / 5;
                int m = k - j * 5;
                if (m == 0) {
                    v = (j < f_in) ? Xa[(long)bL * sXa + (long)nL * snXa + (long)j * sjXa]
                                   : XbT[(long)(j - f_in) * GT + growL];
                } else {
                    long off = (long)(m - 1) * 512 + nL;
                    v = (j < f_in) ? Ta[(long)bL * sTa + (long)j * 2048 + off]
                                   : Tb[(long)bL * sTb + (long)(j - f_in) * 2048 + off];
                }
            }
            aR[e] = v;
        }
        #pragma unroll
        for (int s = 0; s < BF; s++) {
            int k = k0 + bRow[s];
            if (k < K) bR[s] = *(const float4*)(W + (long)k * ldW + col0 + bCol[s]);
            else bR[s] = make_float4(0.f, 0.f, 0.f, 0.f);
        }
    };
    auto stT = [&](int buf) {
        #pragma unroll
        for (int e = 0; e < AE; e++) As[buf][ak0 + e][am] = aR[e];
        #pragma unroll
        for (int s = 0; s < BF; s++) *(float4*)&Bs[buf][bRow[s]][bCol[s]] = bR[s];
    };

    float acc[TM][TN];
    #pragma unroll
    for (int i = 0; i < TM; i++)
        #pragma unroll
        for (int j = 0; j < TN; j++) acc[i][j] = 0.f;

    int ntile = (K + BK - 1) / BK;
    ldT(0); stT(0); __syncthreads();
    for (int t = 0; t < ntile; t++) {
        if (t + 1 < ntile) ldT((t + 1) * BK);
        int buf = t & 1;
        #pragma unroll
        for (int kk = 0; kk < BK; kk++) {
            float ar[TM], br[TN];
            #pragma unroll
            for (int i = 0; i < TM / 4; i++)
                *(float4*)&ar[i * 4] = *(const float4*)&As[buf][kk][ty * TM + i * 4];
            #pragma unroll
            for (int j = 0; j < TN / 4; j++)
                *(float4*)&br[j * 4] = *(const float4*)&Bs[buf][kk][tx * TN + j * 4];
            #pragma unroll
            for (int i = 0; i < TM; i++)
                #pragma unroll
                for (int j = 0; j < TN; j++) acc[i][j] += ar[i] * br[j];
        }
        if (t + 1 < ntile) stT(buf ^ 1);
        __syncthreads();
    }

    #pragma unroll
    for (int i = 0; i < TM; i++) {
        int grow = row0 + ty * TM + i;
        #pragma unroll
        for (int j = 0; j < TN; j++) {
            int c = col0 + tx * TN + j;
            float v = acc[i][j] + bias[c];
            if (mode == 0) {
                v = 1.f / (1.f + expf(-v));
                if (c < 64) RHXT[(long)c * GT + grow] = v * HXrow[(long)grow * 64 + c];
                else        Uout[(long)grow * 64 + (c - 64)] = v;
            } else {
                float cc = tanhf(v);
                float u = Urow[(long)grow * 64 + c];
                float hx = HXrow[(long)grow * 64 + c];
                float h = u * hx + (1.f - u) * cc;
                HoutT[(long)c * GT + grow] = h;
                HoutR[(long)grow * 64 + c] = h;
            }
        }
    }
}

// ---------------------------------------------------------------------------
// Small kernels
// ---------------------------------------------------------------------------
__global__ void hist_t_k(const float* __restrict__ hd, float* __restrict__ histT) {
    int idx = blockIdx.x * blockDim.x + threadIdx.x;
    if (idx >= 24 * B_ * N_) return;
    int n = idx & 511;
    int t2 = idx >> 9;
    int b = t2 & 31;
    int row = t2 >> 5;
    int t = row >> 1, c = row & 1;
    histT[(long)row * GT + b * 512 + n] =
        hd[(((long)b * L_ + t) * N_ + n) * 2 + c];
}

__global__ void dec_diff_k(const float* __restrict__ PT,
                           const float* __restrict__ dec,
                           float* __restrict__ TDEC) {
    int b = blockIdx.y;
    int r = blockIdx.x * 256 + threadIdx.x;
    __shared__ float ds[512];
    ds[threadIdx.x] = dec[b * 512 + threadIdx.x];
    ds[threadIdx.x + 256] = dec[b * 512 + threadIdx.x + 256];
    __syncthreads();
    const float* p = PT + (long)b * 512 * 2048 + r;
    float acc = 0.f;
    #pragma unroll 8
    for (int j = 0; j < 512; j++) acc += ds[j] * p[(long)j * 2048];
    TDEC[(long)b * 2048 + r] = acc;
}

__global__ void add_his_k(float* __restrict__ h0r, float* __restrict__ h0T,
                          float* __restrict__ h1r, float* __restrict__ h1T,
                          const float* __restrict__ his) {
    int i = blockIdx.x * blockDim.x + threadIdx.x;
    if (i >= B_ * N_ * U_) return;
    int grow = i >> 6, c = i & 63;
    float v = his[i];
    h0r[i] += v; h1r[i] += v;
    h0T[(long)c * GT + grow] += v;
    h1T[(long)c * GT + grow] += v;
}

__global__ void projT_k(const float* __restrict__ hT, const float* __restrict__ W,
                        const float* __restrict__ bptr, float* __restrict__ decin,
                        float* __restrict__ out, int t) {
    int grow = blockIdx.x * blockDim.x + threadIdx.x;
    if (grow >= B_ * N_) return;
    float s = bptr[0];
    #pragma unroll
    for (int c = 0; c < 64; c++) s += hT[(long)c * GT + grow] * W[c];
    decin[grow] = s;
    out[(long)grow * HOR + t] = s;
}

// ---------------------------------------------------------------------------
// Host orchestration
// ---------------------------------------------------------------------------
struct HPair { float* r; float* t; };

static void diff64(const float* src1, const float* PT, float* TT) {
    difft_k<64, 256, 8, 8><<<dim3(8, 1, B_), 256>>>(64, 64, src1, nullptr, PT, TT, (long)64 * 2048);
}

static void cell(float* S, int f_in,
                 const float* Xa, long sXa, int snXa, long sjXa,
                 const float* xinT_for_diff,
                 const float* Ta, long sTa,
                 HPair hx, HPair hout,
                 const float* Wg, const float* bg,
                 const float* Wc, const float* bc) {
    float* PT    = S + OFF_PT;
    float* TCATT = S + OFF_TCATT;
    float* THXT  = S + OFF_THXT;
    float* TRHXT = S + OFF_TRHXT;
    float* RHXT  = S + OFF_RHXT;
    float* Ub    = S + OFF_U;

    int K = (f_in + 64) * 5;
    const float* TaG;  long sTaG;
    const float* TbG;  long sTbG;

    if (f_in == 64) {
        // merged diffusion of [xinT ; hxT] -> TCATT (B,128,2048)
        difft_k<128, 128, 8, 8><<<dim3(16, 1, B_), 256>>>(
            128, 64, xinT_for_diff, hx.t, PT, TCATT, (long)128 * 2048);
        TaG = TCATT;             sTaG = (long)128 * 2048;
        TbG = TCATT + 64 * 2048; sTbG = (long)128 * 2048;
    } else {
        diff64(hx.t, PT, THXT);
        TaG = Ta;   sTaG = sTa;
        TbG = THXT; sTbG = (long)64 * 2048;
    }

    // gate (Ncols=128, single col block)
    catgemmT_k<128, 128, 8, 8><<<dim3(1, 128), 256>>>(
        K, f_in, Xa, sXa, snXa, sjXa, hx.t, TaG, sTaG, TbG, sTbG,
        Wg, 128, bg, hx.r, nullptr, RHXT, Ub, nullptr, nullptr, 0);

    // diffusion of r*hx
    diff64(RHXT, PT, TRHXT);

    // candidate + GRU combine (Ncols=64)
    catgemmT_k<128, 64, 8, 4><<<dim3(1, 128), 256>>>(
        K, f_in, Xa, sXa, snXa, sjXa, RHXT, TaG, sTaG, TRHXT, (long)64 * 2048,
        Wc, 64, bc, hx.r, Ub, nullptr, nullptr, hout.t, hout.r, 1);
}

extern "C" void kernel_launch(void* const* d_in, const int* in_sizes, int n_in,
                              void* d_out, int out_size) {
    (void)in_sizes; (void)n_in; (void)out_size;
    float* S = nullptr;
    cudaGetSymbolAddress((void**)&S, g_scratch);

    const float* hd   = (const float*)d_in[0];
    const float* hs   = (const float*)d_in[1];
    const float* adj  = (const float*)d_in[2];
    const float* e0Wg = (const float*)d_in[3];
    const float* e0bg = (const float*)d_in[4];
    const float* e0Wc = (const float*)d_in[5];
    const float* e0bc = (const float*)d_in[6];
    const float* e1Wg = (const float*)d_in[7];
    const float* e1bg = (const float*)d_in[8];
    const float* e1Wc = (const float*)d_in[9];
    const float* e1bc = (const float*)d_in[10];
    const float* d0Wg = (const float*)d_in[11];
    const float* d0bg = (const float*)d_in[12];
    const float* d0Wc = (const float*)d_in[13];
    const float* d0bc = (const float*)d_in[14];
    const float* d1Wg = (const float*)d_in[15];
    const float* d1bg = (const float*)d_in[16];
    const float* d1Wc = (const float*)d_in[17];
    const float* d1bc = (const float*)d_in[18];
    const float* prW  = (const float*)d_in[19];
    const float* prb  = (const float*)d_in[20];
    const float* f1W  = (const float*)d_in[21];
    const float* f1b  = (const float*)d_in[22];
    const float* f2W  = (const float*)d_in[23];
    const float* f2b  = (const float*)d_in[24];
    float* out = (float*)d_out;

    float* A0T  = S + OFF_A0T;
    float* A1T  = S + OFF_A1T;
    float* PT   = S + OFF_PT;
    float* TTX  = S + OFF_TTX;
    float* TDEC = S + OFF_TDEC;
    float* HISTT= S + OFF_HISTT;
    float* HIS  = S + OFF_HIS;
    float* FC1  = S + OFF_FC1;
    float* DEC  = S + OFF_DEC;
    float* RS0  = S + OFF_RS0;
    float* RS1  = S + OFF_RS1;

    HPair H[4];
    for (int i = 0; i < 4; i++) {
        H[i].r  = S + OFF_H + (2 * i) * SZ_H1;
        H[i].t  = S + OFF_H + (2 * i + 1) * SZ_H1;
    }

    cudaMemsetAsync(S + OFF_H, 0, 4 * SZ_H1 * sizeof(float));
    cudaMemsetAsync(DEC, 0, (long)B_ * N_ * sizeof(float));

    // ---- supports + transposed stacked diffusion operator PT ----
    rowsum_k<<<(B_ * N_ * 32 + 255) / 256, 256>>>(adj, RS0);
    colsum_k<<<(B_ * N_ + 255) / 256, 256>>>(adj, RS1);
    fill_supports_T<<<(int)(((long)B_ * N_ * N_ + 255) / 256), 256>>>(adj, RS0, RS1, A0T, A1T, PT);
    const long NB = (long)N_ * N_;
    const long PBx = (long)512 * 2048;
    dim3 gp(4, 4, B_);
    sgemm_t<128, 128, 8, 8><<<gp, 256>>>(512, A0T, 512, NB, A0T, 512, NB,
                                         PT + 512, 2048, PBx, 1, nullptr, 0, nullptr);
    sgemm_t<128, 128, 8, 8><<<gp, 256>>>(512, A0T, 512, NB, A1T, 512, NB,
                                         PT + 1024, 2048, PBx, 0, nullptr, 0, nullptr);
    sgemm_t<128, 128, 8, 8><<<gp, 256>>>(512, PT + 1024, 2048, PBx, A1T, 512, NB,
                                         PT + 1536, 2048, PBx, 2, A0T, NB, nullptr);

    // ---- fc_his ----
    sgemm_t<128, 128, 8, 8><<<dim3(2, 128, 1), 256>>>(96, hs, 96, 0, f1W, 256, 0,
                                                      FC1, 256, 0, 3, nullptr, 0, f1b);
    sgemm_t<128, 64, 8, 4><<<dim3(1, 128, 1), 256>>>(256, FC1, 256, 0, f2W, 64, 0,
                                                     HIS, 64, 0, 3, nullptr, 0, f2b);

    // ---- encoder layer-0 input diffusions, all timesteps at once ----
    hist_t_k<<<(24 * B_ * N_ + 255) / 256, 256>>>(hd, HISTT);
    difft_k<64, 256, 8, 8><<<dim3(8, 1, B_), 256>>>(24, 24, HISTT, nullptr, PT,
                                                    TTX, (long)24 * 2048);

    HPair hc0 = H[0], hc1 = H[1], hn0 = H[2], hn1 = H[3];

    // ---- encoder ----
    for (int t = 0; t < L_; t++) {
        cell(S, 2,
             hd + (long)t * N_ * 2, (long)L_ * N_ * 2, 2, 1,
             nullptr,
             TTX + (long)t * 2 * 2048, (long)24 * 2048,
             hc0, hn0, e0Wg, e0bg, e0Wc, e0bc);
        cell(S, 64,
             hn0.t, 512, 1, (long)GT,
             hn0.t, nullptr, 0,
             hc1, hn1, e1Wg, e1bg, e1Wc, e1bc);
        HPair tmp;
        tmp = hc0; hc0 = hn0; hn0 = tmp;
        tmp = hc1; hc1 = hn1; hn1 = tmp;
    }
    add_his_k<<<(B_ * N_ * U_ + 255) / 256, 256>>>(hc0.r, hc0.t, hc1.r, hc1.t, HIS);

    // ---- decoder ----
    for (int t = 0; t < HOR; t++) {
        dec_diff_k<<<dim3(8, B_), 256>>>(PT, DEC, TDEC);
        cell(S, 1,
             DEC, 512, 1, 0,
             nullptr,
             TDEC, (long)2048,
             hc0, hn0, d0Wg, d0bg, d0Wc, d0bc);
        cell(S, 64,
             hn0.t, 512, 1, (long)GT,
             hn0.t, nullptr, 0,
             hc1, hn1, d1Wg, d1bg, d1Wc, d1bc);
        projT_k<<<(B_ * N_ + 255) / 256, 256>>>(hn1.t, prW, prb, DEC, out, t);
        HPair tmp;
        tmp = hc0; hc0 = hn0; hn0 = tmp;
        tmp = hc1; hc1 = hn1; hn1 = tmp;
    }
}

// round 9
// speedup vs baseline: 1.3952x; 1.0982x over previous
#include <cuda_runtime.h>
#include <math.h>

#define B_  32
#define N_  512
#define L_  12
#define U_  64
#define HOR 12

// ---------------------------------------------------------------------------
// Scratch layout (floats)
// ---------------------------------------------------------------------------
constexpr long SZ_NN  = (long)B_ * N_ * N_;          // 8388608
constexpr long GT     = (long)B_ * N_;               // 16384

constexpr long OFF_A0T   = 0;
constexpr long OFF_A1T   = OFF_A0T + SZ_NN;
constexpr long OFF_PT    = OFF_A1T + SZ_NN;               // (B,512,2048)
constexpr long OFF_TCA   = OFF_PT + 4 * SZ_NN;            // (B,128,2048) ping
constexpr long OFF_TCB   = OFF_TCA + (long)B_*128*2048;   // (B,128,2048) pong
constexpr long OFF_ZD    = OFF_TCB + (long)B_*128*2048;   // (B,64,2048) zeros
constexpr long OFF_THXT  = OFF_ZD + (long)B_*64*2048;     // (B,64,2048) dec step0
constexpr long OFF_TRHXT = OFF_THXT + (long)B_*64*2048;   // (B,64,2048)
constexpr long OFF_TTX   = OFF_TRHXT + (long)B_*64*2048;  // (B,24,2048)
constexpr long OFF_TDEC  = OFF_TTX + (long)B_*24*2048;    // (B,2048)
constexpr long OFF_HISTT = OFF_TDEC + (long)B_*2048;      // (24,16384)
constexpr long OFF_U     = OFF_HISTT + 24*GT;             // (16384,64) row
constexpr long OFF_HIS   = OFF_U + 64*GT;                 // (16384,64) row
constexpr long OFF_FC1   = OFF_HIS + 64*GT;               // (16384,256)
constexpr long OFF_DEC   = OFF_FC1 + 256*GT;              // (16384)
constexpr long OFF_RS0   = OFF_DEC + GT;
constexpr long OFF_RS1   = OFF_RS0 + GT;
constexpr long OFF_RHXT  = OFF_RS1 + GT;                  // (64,16384)
constexpr long OFF_H     = OFF_RHXT + 64*GT;              // 8 buffers x 1M
constexpr long SZ_H1 = 64*GT;
constexpr long SCRATCH_TOTAL = OFF_H + 8*SZ_H1;

__device__ float g_scratch[SCRATCH_TOTAL];

// ---------------------------------------------------------------------------
// Support construction (transposed supports)
// ---------------------------------------------------------------------------
__global__ void rowsum_k(const float* __restrict__ adj, float* __restrict__ rs0) {
    int w = (blockIdx.x * blockDim.x + threadIdx.x) >> 5;
    int lane = threadIdx.x & 31;
    if (w >= B_ * N_) return;
    const float* base = adj + (long)w * N_;
    float s = 0.f;
    for (int j = lane; j < N_; j += 32) s += base[j];
    #pragma unroll
    for (int o = 16; o; o >>= 1) s += __shfl_xor_sync(0xffffffffu, s, o);
    if (lane == 0) rs0[w] = s + 1.0f;
}

__global__ void colsum_k(const float* __restrict__ adj, float* __restrict__ rs1) {
    int idx = blockIdx.x * blockDim.x + threadIdx.x;
    if (idx >= B_ * N_) return;
    int b = idx >> 9, i = idx & 511;
    const float* base = adj + (long)b * N_ * N_ + i;
    float s = 1.0f;
    for (int j = 0; j < N_; j++) s += base[(long)j * N_];
    rs1[idx] = s;
}

__global__ void fill_supports_T(const float* __restrict__ adj,
                                const float* __restrict__ rs0,
                                const float* __restrict__ rs1,
                                float* __restrict__ A0T, float* __restrict__ A1T,
                                float* __restrict__ PT) {
    long idx = (long)blockIdx.x * blockDim.x + threadIdx.x;
    if (idx >= (long)B_ * N_ * N_) return;
    int i = (int)(idx & 511);
    long t = idx >> 9;
    int j = (int)(t & 511);
    int b = (int)(t >> 9);
    float d = (i == j) ? 1.f : 0.f;
    float a_ij = adj[((long)b * N_ + i) * N_ + j];
    float a_ji = adj[idx];
    float v0 = (a_ij + d) / rs0[b * N_ + i];
    float v1 = (a_ji + d) / rs1[b * N_ + i];
    A0T[idx] = v0;
    A1T[idx] = v1;
    PT[(long)b * 512 * 2048 + (long)j * 2048 + i] = v0;
}

// ---------------------------------------------------------------------------
// Generic batched SGEMM: C[b] = A[b] @ B[b], tile BMxBNx16.
// epi: 0 none, 1: 2x - I, 2: 2x - extra[b] (ld 512), 3: bias + relu
// ---------------------------------------------------------------------------
template<int BM, int BN, int TM, int TN>
__global__ __launch_bounds__(256, 2)
void sgemm_t(int K,
             const float* __restrict__ A, int lda, long sA,
             const float* __restrict__ Bm, int ldb, long sB,
             float* __restrict__ C, int ldc, long sC,
             int epi, const float* __restrict__ extra, long sE,
             const float* __restrict__ bias)
{
    constexpr int BK = 16;
    constexpr int TX = BN / TN;
    constexpr int AF = BM / 64;
    constexpr int BF = BN / 64;
    __shared__ float As[2][BK][BM + 4];
    __shared__ float Bs[2][BK][BN];
    int bz = blockIdx.z;
    const float* Ab = A + (long)bz * sA;
    const float* Bb = Bm + (long)bz * sB;
    float* Cb = C + (long)bz * sC;
    int row0 = blockIdx.y * BM, col0 = blockIdx.x * BN;
    int tid = threadIdx.x;
    int tx = tid % TX, ty = tid / TX;

    int aRow[AF], aCol[AF], bRow[BF], bCol[BF];
    #pragma unroll
    for (int s = 0; s < AF; s++) { int idx = tid + s * 256; aRow[s] = idx >> 2; aCol[s] = (idx & 3) << 2; }
    #pragma unroll
    for (int s = 0; s < BF; s++) { int idx = tid + s * 256; bRow[s] = idx / (BN / 4); bCol[s] = (idx % (BN / 4)) << 2; }

    float4 aR[AF], bR[BF];

    auto ldT = [&](int k0) {
        #pragma unroll
        for (int s = 0; s < AF; s++) {
            const float* p = Ab + (long)(row0 + aRow[s]) * lda + k0 + aCol[s];
            if (k0 + BK <= K) aR[s] = *(const float4*)p;
            else {
                int k = k0 + aCol[s];
                aR[s].x = (k     < K) ? p[0] : 0.f;
                aR[s].y = (k + 1 < K) ? p[1] : 0.f;
                aR[s].z = (k + 2 < K) ? p[2] : 0.f;
                aR[s].w = (k + 3 < K) ? p[3] : 0.f;
            }
        }
        #pragma unroll
        for (int s = 0; s < BF; s++) {
            int k = k0 + bRow[s];
            if (k < K) bR[s] = *(const float4*)(Bb + (long)k * ldb + col0 + bCol[s]);
            else bR[s] = make_float4(0.f, 0.f, 0.f, 0.f);
        }
    };
    auto stT = [&](int buf) {
        #pragma unroll
        for (int s = 0; s < AF; s++) {
            As[buf][aCol[s]    ][aRow[s]] = aR[s].x;
            As[buf][aCol[s] + 1][aRow[s]] = aR[s].y;
            As[buf][aCol[s] + 2][aRow[s]] = aR[s].z;
            As[buf][aCol[s] + 3][aRow[s]] = aR[s].w;
        }
        #pragma unroll
        for (int s = 0; s < BF; s++)
            *(float4*)&Bs[buf][bRow[s]][bCol[s]] = bR[s];
    };

    float acc[TM][TN];
    #pragma unroll
    for (int i = 0; i < TM; i++)
        #pragma unroll
        for (int j = 0; j < TN; j++) acc[i][j] = 0.f;

    int ntile = (K + BK - 1) / BK;
    ldT(0); stT(0); __syncthreads();
    for (int t = 0; t < ntile; t++) {
        if (t + 1 < ntile) ldT((t + 1) * BK);
        int buf = t & 1;
        #pragma unroll
        for (int kk = 0; kk < BK; kk++) {
            float ar[TM], br[TN];
            #pragma unroll
            for (int i = 0; i < TM / 4; i++)
                *(float4*)&ar[i * 4] = *(const float4*)&As[buf][kk][ty * TM + i * 4];
            #pragma unroll
            for (int j = 0; j < TN / 4; j++)
                *(float4*)&br[j * 4] = *(const float4*)&Bs[buf][kk][tx * TN + j * 4];
            #pragma unroll
            for (int i = 0; i < TM; i++)
                #pragma unroll
                for (int j = 0; j < TN; j++) acc[i][j] += ar[i] * br[j];
        }
        if (t + 1 < ntile) stT(buf ^ 1);
        __syncthreads();
    }

    #pragma unroll
    for (int i = 0; i < TM; i++) {
        int r = row0 + ty * TM + i;
        #pragma unroll
        for (int j = 0; j < TN; j++) {
            int c = col0 + tx * TN + j;
            float v = acc[i][j];
            if (epi == 1) v = 2.f * v - ((r == c) ? 1.f : 0.f);
            else if (epi == 2) v = 2.f * v - extra[(long)bz * sE + (long)r * N_ + c];
            else if (epi == 3) { v += bias[c]; v = fmaxf(v, 0.f); }
            Cb[(long)r * ldc + c] = v;
        }
    }
}

// ---------------------------------------------------------------------------
// Transposed diffusion GEMM:
//   TT[b](MR x 2048) = Aeff[b](MR x 512) @ PT[b](512 x 2048)
// ---------------------------------------------------------------------------
template<int BM, int BN, int TM, int TN>
__global__ __launch_bounds__(256, 2)
void difft_k(int MR, int asplit,
             const float* __restrict__ src1,
             const float* __restrict__ src2,
             const float* __restrict__ PT,
             float* __restrict__ TT, long sT)
{
    constexpr int BK = 16;
    constexpr int TX = BN / TN;
    constexpr int AE = BM * BK / 256;
    constexpr int BF = BK * BN / 1024;
    __shared__ float As[2][BK][BM + 4];
    __shared__ float Bs[2][BK][BN];

    int bz = blockIdx.z;
    int row0 = blockIdx.y * BM, col0 = blockIdx.x * BN;
    int tid = threadIdx.x;
    int tx = tid % TX, ty = tid / TX;

    int am = tid % BM;
    int ak0 = (tid / BM) * AE;
    int r = row0 + am;
    const float* srow = nullptr;
    if (r < asplit) srow = src1 + (long)r * GT + (long)bz * 512;
    else if (r < MR) srow = src2 + (long)(r - asplit) * GT + (long)bz * 512;

    int bRow[BF], bCol[BF];
    #pragma unroll
    for (int s = 0; s < BF; s++) {
        int idx = tid + s * 256;
        bRow[s] = idx / (BN / 4);
        bCol[s] = (idx % (BN / 4)) << 2;
    }

    float aR[AE];
    float4 bR[BF];
    const float* Pb = PT + (long)bz * 512 * 2048;

    auto ldT = [&](int k0) {
        if (srow) {
            #pragma unroll
            for (int e = 0; e < AE; e += 4)
                *(float4*)&aR[e] = *(const float4*)(srow + k0 + ak0 + e);
        } else {
            #pragma unroll
            for (int e = 0; e < AE; e++) aR[e] = 0.f;
        }
        #pragma unroll
        for (int s = 0; s < BF; s++)
            bR[s] = *(const float4*)(Pb + (long)(k0 + bRow[s]) * 2048 + col0 + bCol[s]);
    };
    auto stT = [&](int buf) {
        #pragma unroll
        for (int e = 0; e < AE; e++) As[buf][ak0 + e][am] = aR[e];
        #pragma unroll
        for (int s = 0; s < BF; s++) *(float4*)&Bs[buf][bRow[s]][bCol[s]] = bR[s];
    };

    float acc[TM][TN];
    #pragma unroll
    for (int i = 0; i < TM; i++)
        #pragma unroll
        for (int j = 0; j < TN; j++) acc[i][j] = 0.f;

    constexpr int NT = 512 / BK;
    ldT(0); stT(0); __syncthreads();
    for (int t = 0; t < NT; t++) {
        if (t + 1 < NT) ldT((t + 1) * BK);
        int buf = t & 1;
        #pragma unroll
        for (int kk = 0; kk < BK; kk++) {
            float ar[TM], br[TN];
            #pragma unroll
            for (int i = 0; i < TM / 4; i++)
                *(float4*)&ar[i * 4] = *(const float4*)&As[buf][kk][ty * TM + i * 4];
            #pragma unroll
            for (int j = 0; j < TN / 4; j++)
                *(float4*)&br[j * 4] = *(const float4*)&Bs[buf][kk][tx * TN + j * 4];
            #pragma unroll
            for (int i = 0; i < TM; i++)
                #pragma unroll
                for (int j = 0; j < TN; j++) acc[i][j] += ar[i] * br[j];
        }
        if (t + 1 < NT) stT(buf ^ 1);
        __syncthreads();
    }

    float* Tb = TT + (long)bz * sT;
    #pragma unroll
    for (int i = 0; i < TM; i++) {
        int rr = row0 + ty * TM + i;
        if (rr < MR) {
            #pragma unroll
            for (int j = 0; j < TN; j++) {
                int c = col0 + tx * TN + j;
                Tb[(long)rr * 2048 + c] = acc[i][j];
            }
        }
    }
}

// ---------------------------------------------------------------------------
// Contraction GEMM, transposed (coalesced) A-gather.
// ---------------------------------------------------------------------------
template<int BM, int BN, int TM, int TN>
__global__ __launch_bounds__(256, 2)
void catgemmT_k(int K, int f_in,
                const float* __restrict__ Xa, long sXa, int snXa, long sjXa,
                const float* __restrict__ XbT,
                const float* __restrict__ Ta, long sTa,
                const float* __restrict__ Tb, long sTb,
                const float* __restrict__ W, int ldW,
                const float* __restrict__ bias,
                const float* __restrict__ HXrow,
                const float* __restrict__ Urow,
                float* __restrict__ RHXT, float* __restrict__ Uout,
                float* __restrict__ HoutT, float* __restrict__ HoutR,
                int mode)
{
    constexpr int BK = 16;
    constexpr int TX = BN / TN;
    constexpr int AE = BM * BK / 256;
    constexpr int BF = BK * BN / 1024;
    __shared__ float As[2][BK][BM + 4];
    __shared__ float Bs[2][BK][BN];

    int row0 = blockIdx.y * BM;
    int col0 = blockIdx.x * BN;
    int tid = threadIdx.x;
    int tx = tid % TX, ty = tid / TX;

    int am = tid % BM;
    int ak0 = (tid / BM) * AE;
    int growL = row0 + am;
    int bL = growL >> 9, nL = growL & 511;

    int bRow[BF], bCol[BF];
    #pragma unroll
    for (int s = 0; s < BF; s++) {
        int idx = tid + s * 256;
        bRow[s] = idx / (BN / 4);
        bCol[s] = (idx % (BN / 4)) << 2;
    }

    float aR[AE];
    float4 bR[BF];

    auto ldT = [&](int k0) {
        #pragma unroll
        for (int e = 0; e < AE; e++) {
            int k = k0 + ak0 + e;
            float v = 0.f;
            if (k < K) {
                int j = k / 5;
                int m = k - j * 5;
                if (m == 0) {
                    v = (j < f_in) ? Xa[(long)bL * sXa + (long)nL * snXa + (long)j * sjXa]
                                   : XbT[(long)(j - f_in) * GT + growL];
                } else {
                    long off = (long)(m - 1) * 512 + nL;
                    v = (j < f_in) ? Ta[(long)bL * sTa + (long)j * 2048 + off]
                                   : Tb[(long)bL * sTb + (long)(j - f_in) * 2048 + off];
                }
            }
            aR[e] = v;
        }
        #pragma unroll
        for (int s = 0; s < BF; s++) {
            int k = k0 + bRow[s];
            if (k < K) bR[s] = *(const float4*)(W + (long)k * ldW + col0 + bCol[s]);
            else bR[s] = make_float4(0.f, 0.f, 0.f, 0.f);
        }
    };
    auto stT = [&](int buf) {
        #pragma unroll
        for (int e = 0; e < AE; e++) As[buf][ak0 + e][am] = aR[e];
        #pragma unroll
        for (int s = 0; s < BF; s++) *(float4*)&Bs[buf][bRow[s]][bCol[s]] = bR[s];
    };

    float acc[TM][TN];
    #pragma unroll
    for (int i = 0; i < TM; i++)
        #pragma unroll
        for (int j = 0; j < TN; j++) acc[i][j] = 0.f;

    int ntile = (K + BK - 1) / BK;
    ldT(0); stT(0); __syncthreads();
    for (int t = 0; t < ntile; t++) {
        if (t + 1 < ntile) ldT((t + 1) * BK);
        int buf = t & 1;
        #pragma unroll
        for (int kk = 0; kk < BK; kk++) {
            float ar[TM], br[TN];
            #pragma unroll
            for (int i = 0; i < TM / 4; i++)
                *(float4*)&ar[i * 4] = *(const float4*)&As[buf][kk][ty * TM + i * 4];
            #pragma unroll
            for (int j = 0; j < TN / 4; j++)
                *(float4*)&br[j * 4] = *(const float4*)&Bs[buf][kk][tx * TN + j * 4];
            #pragma unroll
            for (int i = 0; i < TM; i++)
                #pragma unroll
                for (int j = 0; j < TN; j++) acc[i][j] += ar[i] * br[j];
        }
        if (t + 1 < ntile) stT(buf ^ 1);
        __syncthreads();
    }

    #pragma unroll
    for (int i = 0; i < TM; i++) {
        int grow = row0 + ty * TM + i;
        #pragma unroll
        for (int j = 0; j < TN; j++) {
            int c = col0 + tx * TN + j;
            float v = acc[i][j] + bias[c];
            if (mode == 0) {
                v = 1.f / (1.f + expf(-v));
                if (c < 64) RHXT[(long)c * GT + grow] = v * HXrow[(long)grow * 64 + c];
                else        Uout[(long)grow * 64 + (c - 64)] = v;
            } else {
                float cc = tanhf(v);
                float u = Urow[(long)grow * 64 + c];
                float hx = HXrow[(long)grow * 64 + c];
                float h = u * hx + (1.f - u) * cc;
                HoutT[(long)c * GT + grow] = h;
                HoutR[(long)grow * 64 + c] = h;
            }
        }
    }
}

// ---------------------------------------------------------------------------
// Small kernels
// ---------------------------------------------------------------------------
__global__ void hist_t_k(const float* __restrict__ hd, float* __restrict__ histT) {
    int idx = blockIdx.x * blockDim.x + threadIdx.x;
    if (idx >= 24 * B_ * N_) return;
    int n = idx & 511;
    int t2 = idx >> 9;
    int b = t2 & 31;
    int row = t2 >> 5;
    int t = row >> 1, c = row & 1;
    histT[(long)row * GT + b * 512 + n] =
        hd[(((long)b * L_ + t) * N_ + n) * 2 + c];
}

__global__ void dec_diff_k(const float* __restrict__ PT,
                           const float* __restrict__ dec,
                           float* __restrict__ TDEC) {
    int b = blockIdx.y;
    int r = blockIdx.x * 256 + threadIdx.x;
    __shared__ float ds[512];
    ds[threadIdx.x] = dec[b * 512 + threadIdx.x];
    ds[threadIdx.x + 256] = dec[b * 512 + threadIdx.x + 256];
    __syncthreads();
    const float* p = PT + (long)b * 512 * 2048 + r;
    float acc = 0.f;
    #pragma unroll 8
    for (int j = 0; j < 512; j++) acc += ds[j] * p[(long)j * 2048];
    TDEC[(long)b * 2048 + r] = acc;
}

__global__ void add_his_k(float* __restrict__ h0r, float* __restrict__ h0T,
                          float* __restrict__ h1r, float* __restrict__ h1T,
                          const float* __restrict__ his) {
    int i = blockIdx.x * blockDim.x + threadIdx.x;
    if (i >= B_ * N_ * U_) return;
    int grow = i >> 6, c = i & 63;
    float v = his[i];
    h0r[i] += v; h1r[i] += v;
    h0T[(long)c * GT + grow] += v;
    h1T[(long)c * GT + grow] += v;
}

__global__ void projT_k(const float* __restrict__ hT, const float* __restrict__ W,
                        const float* __restrict__ bptr, float* __restrict__ decin,
                        float* __restrict__ out, int t) {
    int grow = blockIdx.x * blockDim.x + threadIdx.x;
    if (grow >= B_ * N_) return;
    float s = bptr[0];
    #pragma unroll
    for (int c = 0; c < 64; c++) s += hT[(long)c * GT + grow] * W[c];
    decin[grow] = s;
    out[(long)grow * HOR + t] = s;
}

// ---------------------------------------------------------------------------
// Host orchestration
// ---------------------------------------------------------------------------
struct HPair { float* r; float* t; };

static void diff64(const float* src1, const float* PT, float* TT) {
    difft_k<64, 256, 8, 8><<<dim3(8, 1, B_), 256>>>(64, 64, src1, nullptr, PT, TT, (long)64 * 2048);
}

// layer-0 cell: hx diffusion supplied externally (Tb, sTb).
static void cell0(float* S, int f_in,
                  const float* Xa, long sXa, int snXa, long sjXa,
                  const float* Ta, long sTa,
                  const float* Tb, long sTb,
                  HPair hx, HPair hout,
                  const float* Wg, const float* bg,
                  const float* Wc, const float* bc) {
    float* PT    = S + OFF_PT;
    float* TRHXT = S + OFF_TRHXT;
    float* RHXT  = S + OFF_RHXT;
    float* Ub    = S + OFF_U;
    int K = (f_in + 64) * 5;

    catgemmT_k<64, 128, 4, 8><<<dim3(1, 256), 256>>>(
        K, f_in, Xa, sXa, snXa, sjXa, hx.t, Ta, sTa, Tb, sTb,
        Wg, 128, bg, hx.r, nullptr, RHXT, Ub, nullptr, nullptr, 0);
    diff64(RHXT, PT, TRHXT);
    catgemmT_k<64, 64, 4, 4><<<dim3(1, 256), 256>>>(
        K, f_in, Xa, sXa, snXa, sjXa, RHXT, Ta, sTa, TRHXT, (long)64 * 2048,
        Wc, 64, bc, hx.r, Ub, nullptr, nullptr, hout.t, hout.r, 1);
}

// layer-1 cell: computes merged diffusion of [xinT ; hxT] into tcatt (ping-pong).
static void cell1(float* S, const float* xinT, HPair hx, HPair hout,
                  float* tcatt,
                  const float* Wg, const float* bg,
                  const float* Wc, const float* bc) {
    float* PT    = S + OFF_PT;
    float* TRHXT = S + OFF_TRHXT;
    float* RHXT  = S + OFF_RHXT;
    float* Ub    = S + OFF_U;
    const long sTC = (long)128 * 2048;
    int K = 640;

    difft_k<128, 128, 8, 8><<<dim3(16, 1, B_), 256>>>(
        128, 64, xinT, hx.t, PT, tcatt, sTC);
    catgemmT_k<64, 128, 4, 8><<<dim3(1, 256), 256>>>(
        K, 64, xinT, 512, 1, (long)GT, hx.t, tcatt, sTC, tcatt + 64 * 2048, sTC,
        Wg, 128, bg, hx.r, nullptr, RHXT, Ub, nullptr, nullptr, 0);
    diff64(RHXT, PT, TRHXT);
    catgemmT_k<64, 64, 4, 4><<<dim3(1, 256), 256>>>(
        K, 64, xinT, 512, 1, (long)GT, RHXT, tcatt, sTC, TRHXT, (long)64 * 2048,
        Wc, 64, bc, hx.r, Ub, nullptr, nullptr, hout.t, hout.r, 1);
}

extern "C" void kernel_launch(void* const* d_in, const int* in_sizes, int n_in,
                              void* d_out, int out_size) {
    (void)in_sizes; (void)n_in; (void)out_size;
    float* S = nullptr;
    cudaGetSymbolAddress((void**)&S, g_scratch);

    const float* hd   = (const float*)d_in[0];
    const float* hs   = (const float*)d_in[1];
    const float* adj  = (const float*)d_in[2];
    const float* e0Wg = (const float*)d_in[3];
    const float* e0bg = (const float*)d_in[4];
    const float* e0Wc = (const float*)d_in[5];
    const float* e0bc = (const float*)d_in[6];
    const float* e1Wg = (const float*)d_in[7];
    const float* e1bg = (const float*)d_in[8];
    const float* e1Wc = (const float*)d_in[9];
    const float* e1bc = (const float*)d_in[10];
    const float* d0Wg = (const float*)d_in[11];
    const float* d0bg = (const float*)d_in[12];
    const float* d0Wc = (const float*)d_in[13];
    const float* d0bc = (const float*)d_in[14];
    const float* d1Wg = (const float*)d_in[15];
    const float* d1bg = (const float*)d_in[16];
    const float* d1Wc = (const float*)d_in[17];
    const float* d1bc = (const float*)d_in[18];
    const float* prW  = (const float*)d_in[19];
    const float* prb  = (const float*)d_in[20];
    const float* f1W  = (const float*)d_in[21];
    const float* f1b  = (const float*)d_in[22];
    const float* f2W  = (const float*)d_in[23];
    const float* f2b  = (const float*)d_in[24];
    float* out = (float*)d_out;

    float* A0T  = S + OFF_A0T;
    float* A1T  = S + OFF_A1T;
    float* PT   = S + OFF_PT;
    float* TCA  = S + OFF_TCA;
    float* TCB  = S + OFF_TCB;
    float* ZD   = S + OFF_ZD;
    float* THXT = S + OFF_THXT;
    float* TTX  = S + OFF_TTX;
    float* TDEC = S + OFF_TDEC;
    float* HISTT= S + OFF_HISTT;
    float* HIS  = S + OFF_HIS;
    float* FC1  = S + OFF_FC1;
    float* DEC  = S + OFF_DEC;
    float* RS0  = S + OFF_RS0;
    float* RS1  = S + OFF_RS1;

    HPair H[4];
    for (int i = 0; i < 4; i++) {
        H[i].r  = S + OFF_H + (2 * i) * SZ_H1;
        H[i].t  = S + OFF_H + (2 * i + 1) * SZ_H1;
    }

    cudaMemsetAsync(S + OFF_H, 0, 4 * SZ_H1 * sizeof(float));
    cudaMemsetAsync(DEC, 0, (long)B_ * N_ * sizeof(float));
    cudaMemsetAsync(ZD, 0, (long)B_ * 64 * 2048 * sizeof(float));

    // ---- supports + transposed stacked diffusion operator PT ----
    rowsum_k<<<(B_ * N_ * 32 + 255) / 256, 256>>>(adj, RS0);
    colsum_k<<<(B_ * N_ + 255) / 256, 256>>>(adj, RS1);
    fill_supports_T<<<(int)(((long)B_ * N_ * N_ + 255) / 256), 256>>>(adj, RS0, RS1, A0T, A1T, PT);
    const long NB = (long)N_ * N_;
    const long PBx = (long)512 * 2048;
    dim3 gp(4, 4, B_);
    sgemm_t<128, 128, 8, 8><<<gp, 256>>>(512, A0T, 512, NB, A0T, 512, NB,
                                         PT + 512, 2048, PBx, 1, nullptr, 0, nullptr);
    sgemm_t<128, 128, 8, 8><<<gp, 256>>>(512, A0T, 512, NB, A1T, 512, NB,
                                         PT + 1024, 2048, PBx, 0, nullptr, 0, nullptr);
    sgemm_t<128, 128, 8, 8><<<gp, 256>>>(512, PT + 1024, 2048, PBx, A1T, 512, NB,
                                         PT + 1536, 2048, PBx, 2, A0T, NB, nullptr);

    // ---- fc_his ----
    sgemm_t<128, 128, 8, 8><<<dim3(2, 128, 1), 256>>>(96, hs, 96, 0, f1W, 256, 0,
                                                      FC1, 256, 0, 3, nullptr, 0, f1b);
    sgemm_t<128, 64, 8, 4><<<dim3(1, 128, 1), 256>>>(256, FC1, 256, 0, f2W, 64, 0,
                                                     HIS, 64, 0, 3, nullptr, 0, f2b);

    // ---- encoder layer-0 input diffusions, all timesteps at once ----
    hist_t_k<<<(24 * B_ * N_ + 255) / 256, 256>>>(hd, HISTT);
    difft_k<64, 256, 8, 8><<<dim3(8, 1, B_), 256>>>(24, 24, HISTT, nullptr, PT,
                                                    TTX, (long)24 * 2048);

    HPair hc0 = H[0], hc1 = H[1], hn0 = H[2], hn1 = H[3];
    float* prevTC = nullptr;   // layer-1 merged diffusion of previous step

    // ---- encoder ----
    for (int t = 0; t < L_; t++) {
        const float* Tb = (t == 0) ? ZD : prevTC;
        long sTb = (t == 0) ? (long)64 * 2048 : (long)128 * 2048;
        cell0(S, 2,
              hd + (long)t * N_ * 2, (long)L_ * N_ * 2, 2, 1,
              TTX + (long)t * 2 * 2048, (long)24 * 2048,
              Tb, sTb,
              hc0, hn0, e0Wg, e0bg, e0Wc, e0bc);
        float* tc = (prevTC == TCA) ? TCB : TCA;
        cell1(S, hn0.t, hc1, hn1, tc, e1Wg, e1bg, e1Wc, e1bc);
        prevTC = tc;
        HPair tmp;
        tmp = hc0; hc0 = hn0; hn0 = tmp;
        tmp = hc1; hc1 = hn1; hn1 = tmp;
    }
    add_his_k<<<(B_ * N_ * U_ + 255) / 256, 256>>>(hc0.r, hc0.t, hc1.r, hc1.t, HIS);

    // ---- decoder ----
    for (int t = 0; t < HOR; t++) {
        dec_diff_k<<<dim3(8, B_), 256>>>(PT, DEC, TDEC);
        const float* Tb;
        long sTb;
        if (t == 0) {
            // add_his invalidated cached diffusion of h0 — recompute explicitly
            diff64(hc0.t, PT, THXT);
            Tb = THXT; sTb = (long)64 * 2048;
        } else {
            Tb = prevTC; sTb = (long)128 * 2048;
        }
        cell0(S, 1,
              DEC, 512, 1, 0,
              TDEC, (long)2048,
              Tb, sTb,
              hc0, hn0, d0Wg, d0bg, d0Wc, d0bc);
        float* tc = (prevTC == TCA) ? TCB : TCA;
        cell1(S, hn0.t, hc1, hn1, tc, d1Wg, d1bg, d1Wc, d1bc);
        prevTC = tc;
        projT_k<<<(B_ * N_ + 255) / 256, 256>>>(hn1.t, prW, prb, DEC, out, t);
        HPair tmp;
        tmp = hc0; hc0 = hn0; hn0 = tmp;
        tmp = hc1; hc1 = hn1; hn1 = tmp;
    }
}